// round 9
// baseline (speedup 1.0000x reference)
#include <cuda_runtime.h>
#include <cuda_bf16.h>
#include <math_constants.h>
#include <cstdint>
#include <cstddef>

#define DIM 1024
#define NSEG 1024
#define SEQ 2048

// tile = 128 rows x 64 bf16 cols (16KB), SW128. Pairs [hi,lo] stored adjacently.
#define LAYER_W_ELEMS  (8 * 16 * 2 * 8192)   // 8 nb x 16 kt x {hi,lo}
#define POOLER_W_ELEMS (8 * 32 * 2 * 8192)
#define AX_STRIDE      (8 * 16 * 2 * 8192)   // per-tower A' buffer (4MB)
#define Y_STRIDE       (NSEG * DIM)

__device__ __align__(16) __nv_bfloat16 g_Wbf[POOLER_W_ELEMS + 13 * LAYER_W_ELEMS];
__device__ __align__(16) __nv_bfloat16 g_Abf[8 * 32 * 2 * 8192];  // pooler A'
__device__ __align__(16) __nv_bfloat16 g_Ax [3 * AX_STRIDE];      // per-tower working A'
__device__ __align__(16) __nv_bfloat16 g_Ap [AX_STRIDE];          // pool-block output A'
__device__ __align__(16) float g_y[3 * Y_STRIDE];
__device__ __align__(16) float g_a[3 * Y_STRIDE];

// ---------------- PTX helpers (base sm_90 PTX only) ----------------
__device__ __forceinline__ uint32_t smem_u32(const void* p) {
    uint32_t a;
    asm("{ .reg .u64 t; cvta.to.shared.u64 t, %1; cvt.u32.u64 %0, t; }" : "=r"(a) : "l"(p));
    return a;
}
__device__ __forceinline__ void mbar_init(uint32_t a, uint32_t cnt) {
    asm volatile("mbarrier.init.shared.b64 [%0], %1;" :: "r"(a), "r"(cnt) : "memory");
}
__device__ __forceinline__ void mbar_expect_tx(uint32_t a, uint32_t bytes) {
    asm volatile("mbarrier.arrive.expect_tx.shared.b64 _, [%0], %1;" :: "r"(a), "r"(bytes) : "memory");
}
__device__ __forceinline__ void mbar_wait(uint32_t a, uint32_t parity) {
    asm volatile(
        "{\n\t.reg .pred P;\n\t"
        "WL_%=:\n\t"
        "mbarrier.try_wait.parity.acquire.cta.shared::cta.b64 P, [%0], %1, 0x989680;\n\t"
        "@!P bra WL_%=;\n\t}"
        :: "r"(a), "r"(parity) : "memory");
}
__device__ __forceinline__ void mbar_inval(uint32_t a) {
    asm volatile("mbarrier.inval.shared.b64 [%0];" :: "r"(a) : "memory");
}
__device__ __forceinline__ void bulk_g2s(uint32_t dst, const void* src, uint32_t bytes, uint32_t mbar) {
    asm volatile("cp.async.bulk.shared::cta.global.mbarrier::complete_tx::bytes [%0], [%1], %2, [%3];"
                 :: "r"(dst), "l"(src), "r"(bytes), "r"(mbar) : "memory");
}
__device__ __forceinline__ void ldsm4(uint32_t& r0, uint32_t& r1, uint32_t& r2, uint32_t& r3, uint32_t addr) {
    asm volatile("ldmatrix.sync.aligned.m8n8.x4.shared.b16 {%0,%1,%2,%3}, [%4];"
                 : "=r"(r0), "=r"(r1), "=r"(r2), "=r"(r3) : "r"(addr));
}
__device__ __forceinline__ void mma16816(float* c, const uint32_t* a, uint32_t b0, uint32_t b1) {
    asm volatile(
        "mma.sync.aligned.m16n8k16.row.col.f32.bf16.bf16.f32 "
        "{%0,%1,%2,%3}, {%4,%5,%6,%7}, {%8,%9}, {%0,%1,%2,%3};"
        : "+f"(c[0]), "+f"(c[1]), "+f"(c[2]), "+f"(c[3])
        : "r"(a[0]), "r"(a[1]), "r"(a[2]), "r"(a[3]), "r"(b0), "r"(b1));
}

#define SW128(o) ((o) ^ (((o) >> 3) & 0x70))

__device__ __forceinline__ void split8(const float* v, uint4& hi, uint4& lo) {
    __nv_bfloat16* hp = (__nv_bfloat16*)&hi;
    __nv_bfloat16* lp = (__nv_bfloat16*)&lo;
    #pragma unroll
    for (int i = 0; i < 8; ++i) {
        __nv_bfloat16 hb = __float2bfloat16(v[i]);
        hp[i] = hb;
        lp[i] = __float2bfloat16(v[i] - __bfloat162float(hb));
    }
}
// store an 8-value group into paired tile layout: tiles (mb,kt) -> [hi(16KB), lo(16KB)]
__device__ __forceinline__ void store_pair(__nv_bfloat16* base, int mb, int TK, int trow,
                                           int kprime, const uint4& hi, const uint4& lo) {
    int kt = kprime >> 6;
    int tcol = kprime & 63;
    uint32_t off = SW128((uint32_t)trow * 128u + (uint32_t)tcol * 2u);
    char* t0 = (char*)(base + (((size_t)(mb * TK + kt) * 2) << 13));
    *(uint4*)(t0 + off) = hi;
    *(uint4*)(t0 + 16384 + off) = lo;
}
// store 2 adjacent values (4B) into paired tile layout (SW128 keeps 4B alignment)
__device__ __forceinline__ void store_pair2(__nv_bfloat16* base, int mb, int TK, int trow,
                                            int col, float v0, float v1) {
    int kt = col >> 6;
    int tcol = col & 63;
    uint32_t off = SW128((uint32_t)trow * 128u + (uint32_t)tcol * 2u);
    char* t0 = (char*)(base + (((size_t)(mb * TK + kt) * 2) << 13));
    __nv_bfloat16 h0 = __float2bfloat16(v0);
    __nv_bfloat16 h1 = __float2bfloat16(v1);
    __nv_bfloat16 l0 = __float2bfloat16(v0 - __bfloat162float(h0));
    __nv_bfloat16 l1 = __float2bfloat16(v1 - __bfloat162float(h1));
    __nv_bfloat162 hw = __halves2bfloat162(h0, h1);
    __nv_bfloat162 lw = __halves2bfloat162(l0, l1);
    *(__nv_bfloat162*)(t0 + off) = hw;
    *(__nv_bfloat162*)(t0 + 16384 + off) = lw;
}

// ---------------- ragged pooling -> pooler A' paired tiles (TK=32) ----------------
__global__ __launch_bounds__(128)
void pool_kernel(const float* __restrict__ h, const int* __restrict__ turns,
                 const int* __restrict__ parts, __nv_bfloat16* __restrict__ Abf) {
    int s = blockIdx.x;
    int b = s >> 4;
    int j = s & 15;
    int start = 1;
    #pragma unroll
    for (int t = 0; t < 16; ++t)
        if (t < j) start += parts[b * 16 + t];
    int count = parts[b * 16 + j];
    bool valid = (j < turns[b]);
    int c0 = threadIdx.x * 8;
    const float* base = h + ((size_t)b * SEQ + start) * DIM + c0;

    float mx[8], sm[8];
    #pragma unroll
    for (int i = 0; i < 8; ++i) { mx[i] = -CUDART_INF_F; sm[i] = 0.f; }
    if (valid) {
        int p = 0;
        for (; p + 1 < count; p += 2) {
            float4 v0 = *(const float4*)(base + (size_t)p * DIM);
            float4 v1 = *(const float4*)(base + (size_t)p * DIM + 4);
            float4 w0 = *(const float4*)(base + (size_t)(p + 1) * DIM);
            float4 w1 = *(const float4*)(base + (size_t)(p + 1) * DIM + 4);
            float v[8] = {v0.x, v0.y, v0.z, v0.w, v1.x, v1.y, v1.z, v1.w};
            float w[8] = {w0.x, w0.y, w0.z, w0.w, w1.x, w1.y, w1.z, w1.w};
            #pragma unroll
            for (int i = 0; i < 8; ++i) {
                mx[i] = fmaxf(mx[i], fmaxf(v[i], w[i]));
                sm[i] += v[i] + w[i];
            }
        }
        if (p < count) {
            float4 v0 = *(const float4*)(base + (size_t)p * DIM);
            float4 v1 = *(const float4*)(base + (size_t)p * DIM + 4);
            float v[8] = {v0.x, v0.y, v0.z, v0.w, v1.x, v1.y, v1.z, v1.w};
            #pragma unroll
            for (int i = 0; i < 8; ++i) { mx[i] = fmaxf(mx[i], v[i]); sm[i] += v[i]; }
        }
        float inv = 1.0f / (float)count;
        #pragma unroll
        for (int i = 0; i < 8; ++i) sm[i] *= inv;
    } else {
        #pragma unroll
        for (int i = 0; i < 8; ++i) sm[i] = CUDART_NAN_F;
    }
    int mb = s >> 7, trow = s & 127;
    uint4 hi, lo;
    split8(mx, hi, lo);
    store_pair(Abf, mb, 32, trow, c0, hi, lo);
    split8(sm, hi, lo);
    store_pair(Abf, mb, 32, trow, 1024 + c0, hi, lo);
}

// ---------------- weight conversion body ----------------
__device__ __forceinline__ void wconv_body(const float* __restrict__ W, __nv_bfloat16* __restrict__ dst,
                                           int nb, int kt, int TK) {
    __shared__ float sh[64][129];
    int k0 = kt * 64;
    int tid = threadIdx.x;
    for (int idx = tid; idx < 2048; idx += 256) {
        int row = idx >> 5, c4 = (idx & 31) * 4;
        float4 v = *(const float4*)&W[(size_t)(k0 + row) * 1024 + nb * 128 + c4];
        sh[row][c4] = v.x; sh[row][c4 + 1] = v.y; sh[row][c4 + 2] = v.z; sh[row][c4 + 3] = v.w;
    }
    __syncthreads();
    int n = tid >> 1, kc0 = (tid & 1) * 32;
    char* t0 = (char*)(dst + (((size_t)(nb * TK + kt) * 2) << 13));
    #pragma unroll
    for (int g = 0; g < 4; ++g) {
        uint4 h4, l4;
        __nv_bfloat16* hp = (__nv_bfloat16*)&h4;
        __nv_bfloat16* lp = (__nv_bfloat16*)&l4;
        #pragma unroll
        for (int i = 0; i < 8; ++i) {
            float v = sh[kc0 + g * 8 + i][n];
            __nv_bfloat16 hb = __float2bfloat16(v);
            hp[i] = hb;
            lp[i] = __float2bfloat16(v - __bfloat162float(hb));
        }
        uint32_t off = SW128((uint32_t)n * 128u + (uint32_t)(kc0 + g * 8) * 2u);
        *(uint4*)(t0 + off) = h4;
        *(uint4*)(t0 + 16384 + off) = l4;
    }
}

__global__ __launch_bounds__(256)
void wconv_pooler(const float* __restrict__ W, __nv_bfloat16* __restrict__ dst) {
    wconv_body(W, dst, blockIdx.x, blockIdx.y, 32);
}
__global__ __launch_bounds__(256)
void wconv_all(const float* __restrict__ pool_W, const float* __restrict__ emo_Ws,
               const float* __restrict__ act_Ws, const float* __restrict__ int_Ws,
               __nv_bfloat16* __restrict__ wl) {
    int z = blockIdx.z;
    const float* W;
    if (z == 0) W = pool_W;
    else {
        int t = (z - 1) >> 2, k = (z - 1) & 3;
        const float* Ws = (t == 0) ? emo_Ws : (t == 1) ? act_Ws : int_Ws;
        W = Ws + (size_t)k * DIM * DIM;
    }
    wconv_body(W, wl + (size_t)z * LAYER_W_ELEMS, blockIdx.x, blockIdx.y, 16);
}

// ---------------- HMMA bf16x3 GEMM v5: full-fragment kk steps, max RAW distance ----------------
// CTA 128(M) x 64(N); grid (16 nb-half, 8 mb, nz). Stage = {Ah,Al,Wh,Wl} = 48KB, NSTAGE=2.
// Warp tile 32(M) x 32(N), 4m x 2n warps. Per kk: load ALL fragments (8 ldsm4),
// then 24 MMAs ordered j-major/i-inner (dependent-acc distance = 8 issues).
#define NSTAGE 2
#define STAGE_BYTES 49152
template <int EPI>
__global__ __launch_bounds__(256, 2)
void mma_gemm(const __nv_bfloat16* __restrict__ Ab, size_t az,
              const __nv_bfloat16* __restrict__ Wb, size_t wz,
              float* __restrict__ Yb, size_t yz, int TK,
              const float* __restrict__ bias, __nv_bfloat16* __restrict__ Aout) {
    extern __shared__ char smem[];
    uint32_t base = smem_u32(smem);
    uint32_t tbase = (base + 1023u) & ~1023u;
    uint32_t ctrl = tbase + NSTAGE * STAGE_BYTES;

    int tid = threadIdx.x;
    int wid = tid >> 5, lane = tid & 31;
    int wm = (wid & 3) * 32;     // 4 m-warps
    int wn = (wid >> 2) * 32;    // 2 n-warps
    int z = blockIdx.z;

    if (tid == 0) { mbar_init(ctrl, 1); mbar_init(ctrl + 8, 1); }
    __syncthreads();

    const char* Aptr = (const char*)(Ab + (size_t)z * az) + (size_t)blockIdx.y * TK * 32768;
    const char* Wptr = (const char*)(Wb + (size_t)z * wz) + (size_t)(blockIdx.x >> 1) * TK * 32768;
    uint32_t bhalf = (blockIdx.x & 1) * 8192u;

    if (tid == 0) {
        #pragma unroll
        for (int i = 0; i < NSTAGE; ++i) {
            uint32_t mb = ctrl + i * 8;
            mbar_expect_tx(mb, STAGE_BYTES);
            bulk_g2s(tbase + i * STAGE_BYTES,         Aptr + (size_t)i * 32768, 32768u, mb);
            bulk_g2s(tbase + i * STAGE_BYTES + 32768, Wptr + (size_t)i * 32768 + bhalf, 8192u, mb);
            bulk_g2s(tbase + i * STAGE_BYTES + 40960, Wptr + (size_t)i * 32768 + 16384 + bhalf, 8192u, mb);
        }
    }

    // A fragment addresses: 2 m-blocks of 16 rows
    int rA[2], xA[2];
    #pragma unroll
    for (int i = 0; i < 2; ++i) {
        int row = wm + i * 16 + (lane & 15);
        rA[i] = row * 128;
        xA[i] = (row & 7) << 4;
    }
    int hiA = (lane >> 4) << 4;
    // B fragment addresses: two 16-col groups (wn..wn+15, wn+16..wn+31)
    int rowB = wn + (lane & 7) + ((lane >> 4) << 3);
    int rB = rowB * 128;                 // group 0; group 1 at +16 rows = +2048B
    int xB = (rowB & 7) << 4;
    int hiB = ((lane >> 3) & 1) << 4;

    float acc[2][4][4];
    #pragma unroll
    for (int i = 0; i < 2; ++i)
        #pragma unroll
        for (int j = 0; j < 4; ++j)
            #pragma unroll
            for (int q = 0; q < 4; ++q) acc[i][j][q] = 0.f;

    uint32_t ah[2][2][4], al[2][2][4], wh[2][8], wl[2][8];

#define LOAD_KK(buf, kk_)                                                                  \
    do {                                                                                   \
        uint32_t boff = (uint32_t)(((kk_) << 5) + hiB) ^ (uint32_t)xB;                     \
        ldsm4(wh[buf][0], wh[buf][1], wh[buf][2], wh[buf][3], sWh + rB + boff);            \
        ldsm4(wh[buf][4], wh[buf][5], wh[buf][6], wh[buf][7], sWh + rB + 2048 + boff);     \
        ldsm4(wl[buf][0], wl[buf][1], wl[buf][2], wl[buf][3], sWl + rB + boff);            \
        ldsm4(wl[buf][4], wl[buf][5], wl[buf][6], wl[buf][7], sWl + rB + 2048 + boff);     \
        uint32_t aoff0 = (uint32_t)(((kk_) << 5) + hiA) ^ (uint32_t)xA[0];                 \
        uint32_t aoff1 = (uint32_t)(((kk_) << 5) + hiA) ^ (uint32_t)xA[1];                 \
        ldsm4(ah[buf][0][0], ah[buf][0][1], ah[buf][0][2], ah[buf][0][3], sAh + rA[0] + aoff0); \
        ldsm4(ah[buf][1][0], ah[buf][1][1], ah[buf][1][2], ah[buf][1][3], sAh + rA[1] + aoff1); \
        ldsm4(al[buf][0][0], al[buf][0][1], al[buf][0][2], al[buf][0][3], sAl + rA[0] + aoff0); \
        ldsm4(al[buf][1][0], al[buf][1][1], al[buf][1][2], al[buf][1][3], sAl + rA[1] + aoff1); \
    } while (0)

    for (int kt = 0; kt < TK; ++kt) {
        int s = kt & 1;
        mbar_wait(ctrl + s * 8, (kt >> 1) & 1);
        uint32_t sAh = tbase + s * STAGE_BYTES;
        uint32_t sAl = sAh + 16384u;
        uint32_t sWh = sAh + 32768u;
        uint32_t sWl = sAh + 40960u;

        LOAD_KK(0, 0);
        #pragma unroll
        for (int kk = 0; kk < 4; ++kk) {
            const int b = kk & 1;
            if (kk < 3) LOAD_KK(b ^ 1, kk + 1);
            // pass 1: ah x wh  (8 MMAs, acc distance 8)
            #pragma unroll
            for (int j = 0; j < 4; ++j) {
                mma16816(acc[0][j], ah[b][0], wh[b][2 * j], wh[b][2 * j + 1]);
                mma16816(acc[1][j], ah[b][1], wh[b][2 * j], wh[b][2 * j + 1]);
            }
            // pass 2: ah x wl
            #pragma unroll
            for (int j = 0; j < 4; ++j) {
                mma16816(acc[0][j], ah[b][0], wl[b][2 * j], wl[b][2 * j + 1]);
                mma16816(acc[1][j], ah[b][1], wl[b][2 * j], wl[b][2 * j + 1]);
            }
            // pass 3: al x wh
            #pragma unroll
            for (int j = 0; j < 4; ++j) {
                mma16816(acc[0][j], al[b][0], wh[b][2 * j], wh[b][2 * j + 1]);
                mma16816(acc[1][j], al[b][1], wh[b][2 * j], wh[b][2 * j + 1]);
            }
        }
        __syncthreads();
        if (tid == 0 && kt + NSTAGE < TK) {
            int nk = kt + NSTAGE;
            uint32_t mb = ctrl + s * 8;
            mbar_expect_tx(mb, STAGE_BYTES);
            bulk_g2s(sAh,          Aptr + (size_t)nk * 32768, 32768u, mb);
            bulk_g2s(sAh + 32768u, Wptr + (size_t)nk * 32768 + bhalf, 8192u, mb);
            bulk_g2s(sAh + 40960u, Wptr + (size_t)nk * 32768 + 16384 + bhalf, 8192u, mb);
        }
    }
#undef LOAD_KK

    int trow0 = wm + (lane >> 2);
    if (EPI == 0) {
        float* Y = Yb + (size_t)z * yz;
        int r0 = blockIdx.y * 128 + trow0;
        #pragma unroll
        for (int i = 0; i < 2; ++i) {
            #pragma unroll
            for (int j = 0; j < 4; ++j) {
                int row = r0 + i * 16;
                int col = blockIdx.x * 64 + wn + j * 8 + ((lane & 3) << 1);
                *(float2*)&Y[(size_t)row * 1024 + col]       = make_float2(acc[i][j][0], acc[i][j][1]);
                *(float2*)&Y[(size_t)(row + 8) * 1024 + col] = make_float2(acc[i][j][2], acc[i][j][3]);
            }
        }
    } else {
        #pragma unroll
        for (int i = 0; i < 2; ++i) {
            #pragma unroll
            for (int j = 0; j < 4; ++j) {
                int col = blockIdx.x * 64 + wn + j * 8 + ((lane & 3) << 1);
                float b0 = bias[col], b1 = bias[col + 1];
                float v00 = tanhf(acc[i][j][0] + b0);
                float v01 = tanhf(acc[i][j][1] + b1);
                float v10 = tanhf(acc[i][j][2] + b0);
                float v11 = tanhf(acc[i][j][3] + b1);
                store_pair2(Aout, blockIdx.y, 16, trow0 + i * 16,     col, v00, v01);
                store_pair2(Aout, blockIdx.y, 16, trow0 + i * 16 + 8, col, v10, v11);
            }
        }
    }
    __syncthreads();
    if (tid == 0) { mbar_inval(ctrl); mbar_inval(ctrl + 8); }
}

// ---------------- BatchNorm(+tanh), batched over z ----------------
template <bool TILES, bool FP32>
__global__ __launch_bounds__(256)
void bn_kernel(const float* __restrict__ Yb, size_t yz,
               const float* __restrict__ g0, const float* __restrict__ g1, const float* __restrict__ g2,
               const float* __restrict__ be0, const float* __restrict__ be1, const float* __restrict__ be2,
               float* __restrict__ afpB, size_t afz,
               __nv_bfloat16* __restrict__ AtB, size_t atz) {
    __shared__ float ss[32][8], sq[32][8];
    __shared__ float sscale[8], sshift[8];
    int z = blockIdx.y;
    const float* Y   = Yb + (size_t)z * yz;
    const float* g    = (z == 0) ? g0 : (z == 1) ? g1 : g2;
    const float* beta = (z == 0) ? be0 : (z == 1) ? be1 : be2;
    int tid = threadIdx.x;
    int c0 = blockIdx.x * 8;
    int c = tid & 7, rg = tid >> 3;
    float s = 0.f, q = 0.f;
    for (int r = rg; r < 1024; r += 32) {
        float v = Y[(size_t)r * 1024 + c0 + c];
        s += v; q += v * v;
    }
    ss[rg][c] = s; sq[rg][c] = q;
    __syncthreads();
    if (tid < 8) {
        float ts = 0.f, tq = 0.f;
        #pragma unroll
        for (int i = 0; i < 32; ++i) { ts += ss[i][tid]; tq += sq[i][tid]; }
        float mean = ts * (1.f / 1024.f);
        float var  = fmaxf(tq * (1.f / 1024.f) - mean * mean, 0.f);
        float rs   = rsqrtf(var + 1e-5f);
        float sc   = g[c0 + tid] * rs;
        sscale[tid] = sc;
        sshift[tid] = beta[c0 + tid] - mean * sc;
    }
    __syncthreads();
    float sc[8], sh[8];
    #pragma unroll
    for (int i = 0; i < 8; ++i) { sc[i] = sscale[i]; sh[i] = sshift[i]; }
    float* afp = FP32 ? (afpB + (size_t)z * afz) : nullptr;
    __nv_bfloat16* At = TILES ? (AtB + (size_t)z * atz) : nullptr;
    for (int r = tid; r < 1024; r += 256) {
        float4 v0 = *(const float4*)&Y[(size_t)r * 1024 + c0];
        float4 v1 = *(const float4*)&Y[(size_t)r * 1024 + c0 + 4];
        float v[8] = {v0.x, v0.y, v0.z, v0.w, v1.x, v1.y, v1.z, v1.w};
        #pragma unroll
        for (int i = 0; i < 8; ++i) v[i] = tanhf(v[i] * sc[i] + sh[i]);
        if (FP32) {
            *(float4*)&afp[(size_t)r * 1024 + c0]     = make_float4(v[0], v[1], v[2], v[3]);
            *(float4*)&afp[(size_t)r * 1024 + c0 + 4] = make_float4(v[4], v[5], v[6], v[7]);
        }
        if (TILES) {
            uint4 hi, lo;
            split8(v, hi, lo);
            store_pair(At, r >> 7, 16, r & 127, c0, hi, lo);
        }
    }
}

// ---------------- batched head GEMMs: grid (128, 3) ----------------
__global__ __launch_bounds__(128)
void final_kernel(const float* __restrict__ Xb, size_t xz,
                  const float* __restrict__ wf0, const float* __restrict__ wf1, const float* __restrict__ wf2,
                  const float* __restrict__ bf0, const float* __restrict__ bf1, const float* __restrict__ bf2,
                  float* __restrict__ outb) {
    __shared__ float sh[8][1024];
    int t = blockIdx.y;
    const int nout = (t == 0) ? 7 : (t == 1) ? 5 : 102;
    const int off  = (t == 0) ? 0 : (t == 1) ? 7 * NSEG : 12 * NSEG;
    const float* X  = Xb + (size_t)t * xz;
    const float* Wf = (t == 0) ? wf0 : (t == 1) ? wf1 : wf2;
    const float* bf = (t == 0) ? bf0 : (t == 1) ? bf1 : bf2;
    float* out = outb + off;

    int r0 = blockIdx.x * 8;
    const float4* Xs = (const float4*)(X + (size_t)r0 * 1024);
    #pragma unroll
    for (int q = 0; q < 16; ++q) {
        int i = threadIdx.x + q * 128;
        int row = i >> 8, col4 = (i & 255);
        *(float4*)&sh[row][col4 * 4] = Xs[(size_t)row * 256 + col4];
    }
    __syncthreads();
    for (int n = threadIdx.x; n < nout; n += 128) {
        float acc[8];
        float bv = bf[n];
        #pragma unroll
        for (int r = 0; r < 8; ++r) acc[r] = bv;
        #pragma unroll 8
        for (int k = 0; k < 1024; ++k) {
            float w = Wf[(size_t)k * nout + n];
            #pragma unroll
            for (int r = 0; r < 8; ++r) acc[r] += sh[r][k] * w;
        }
        #pragma unroll
        for (int r = 0; r < 8; ++r)
            out[(size_t)(r0 + r) * nout + n] = acc[r];
    }
}

// ---------------- launch ----------------
#define GEMM_SMEM (NSTAGE * STAGE_BYTES + 1024 + 64)

extern "C" void kernel_launch(void* const* d_in, const int* in_sizes, int n_in,
                              void* d_out, int out_size) {
    const float* h        = (const float*)d_in[0];
    const int*   turns    = (const int*)  d_in[1];
    const int*   parts    = (const int*)  d_in[2];
    const float* pooler_W = (const float*)d_in[3];
    const float* pooler_b = (const float*)d_in[4];
    const float* pool_W   = (const float*)d_in[5];
    // d_in[6] pool_b: cancelled by BN mean subtraction
    const float* pool_g   = (const float*)d_in[7];
    const float* pool_be  = (const float*)d_in[8];
    const float* emo_Ws   = (const float*)d_in[9];
    const float* emo_gs   = (const float*)d_in[11];
    const float* emo_be   = (const float*)d_in[12];
    const float* emo_Wf   = (const float*)d_in[13];
    const float* emo_bf   = (const float*)d_in[14];
    const float* act_Ws   = (const float*)d_in[15];
    const float* act_gs   = (const float*)d_in[17];
    const float* act_be   = (const float*)d_in[18];
    const float* act_Wf   = (const float*)d_in[19];
    const float* act_bf   = (const float*)d_in[20];
    const float* int_Ws   = (const float*)d_in[21];
    const float* int_gs   = (const float*)d_in[23];
    const float* int_be   = (const float*)d_in[24];
    const float* int_Wf   = (const float*)d_in[25];
    const float* int_bf   = (const float*)d_in[26];
    float* out = (float*)d_out;

    __nv_bfloat16 *Wbf, *Abf, *Ax, *Ap;
    float *y, *a;
    cudaGetSymbolAddress((void**)&Wbf, g_Wbf);
    cudaGetSymbolAddress((void**)&Abf, g_Abf);
    cudaGetSymbolAddress((void**)&Ax,  g_Ax);
    cudaGetSymbolAddress((void**)&Ap,  g_Ap);
    cudaGetSymbolAddress((void**)&y,   g_y);
    cudaGetSymbolAddress((void**)&a,   g_a);
    __nv_bfloat16* wl = Wbf + POOLER_W_ELEMS;

    cudaFuncSetAttribute(mma_gemm<0>, cudaFuncAttributeMaxDynamicSharedMemorySize, GEMM_SMEM);
    cudaFuncSetAttribute(mma_gemm<1>, cudaFuncAttributeMaxDynamicSharedMemorySize, GEMM_SMEM);

    // weights: 2 launches
    wconv_pooler<<<dim3(8, 32), 256>>>(pooler_W, Wbf);
    wconv_all<<<dim3(8, 16, 13), 256>>>(pool_W, emo_Ws, act_Ws, int_Ws, wl);

    // pooling
    pool_kernel<<<NSEG, 128>>>(h, turns, parts, Abf);

    // pooler GEMM + fused tanh(+bias) epilogue -> A'(x0) in Ax[0]
    mma_gemm<1><<<dim3(16, 8, 1), 256, GEMM_SMEM>>>(Abf, 0, Wbf, 0, nullptr, 0, 32, pooler_b, Ax);

    // pool Linear_Block -> Ap (shared input of all 3 towers)
    mma_gemm<0><<<dim3(16, 8, 1), 256, GEMM_SMEM>>>(Ax, 0, wl, 0, y, 0, 16, nullptr, nullptr);
    bn_kernel<true, false><<<dim3(128, 1), 256>>>(y, 0, pool_g, pool_g, pool_g,
                                                  pool_be, pool_be, pool_be,
                                                  nullptr, 0, Ap, 0);

    // tower depths, batched over the 3 towers
    for (int k = 0; k < 4; ++k) {
        const __nv_bfloat16* Ain = (k == 0) ? Ap : Ax;
        size_t az = (k == 0) ? 0 : (size_t)AX_STRIDE;
        mma_gemm<0><<<dim3(16, 8, 3), 256, GEMM_SMEM>>>(Ain, az,
                                                        wl + (size_t)(1 + k) * LAYER_W_ELEMS,
                                                        (size_t)4 * LAYER_W_ELEMS,
                                                        y, Y_STRIDE, 16, nullptr, nullptr);
        if (k < 3)
            bn_kernel<true, false><<<dim3(128, 3), 256>>>(y, Y_STRIDE,
                emo_gs + k * DIM, act_gs + k * DIM, int_gs + k * DIM,
                emo_be + k * DIM, act_be + k * DIM, int_be + k * DIM,
                nullptr, 0, Ax, AX_STRIDE);
        else
            bn_kernel<false, true><<<dim3(128, 3), 256>>>(y, Y_STRIDE,
                emo_gs + k * DIM, act_gs + k * DIM, int_gs + k * DIM,
                emo_be + k * DIM, act_be + k * DIM, int_be + k * DIM,
                a, Y_STRIDE, nullptr, 0);
    }

    // batched heads
    final_kernel<<<dim3(128, 3), 128>>>(a, Y_STRIDE, emo_Wf, act_Wf, int_Wf,
                                        emo_bf, act_bf, int_bf, out);
}

// round 10
// speedup vs baseline: 1.4068x; 1.4068x over previous
#include <cuda_runtime.h>
#include <cuda_bf16.h>
#include <math_constants.h>
#include <cstdint>
#include <cstddef>

#define DIM 1024
#define NSEG 1024
#define SEQ 2048

// tile = 128 rows x 64 bf16 cols (16KB), SW128. Pairs [hi,lo] stored adjacently.
#define LAYER_W_ELEMS  (8 * 16 * 2 * 8192)   // 8 nb x 16 kt x {hi,lo}
#define POOLER_W_ELEMS (8 * 32 * 2 * 8192)
#define AX_STRIDE      (8 * 16 * 2 * 8192)   // per-tower A' buffer (4MB)
#define Y_STRIDE       (NSEG * DIM)

__device__ __align__(16) __nv_bfloat16 g_Wbf[POOLER_W_ELEMS + 13 * LAYER_W_ELEMS];
__device__ __align__(16) __nv_bfloat16 g_Abf[8 * 32 * 2 * 8192];  // pooler A'
__device__ __align__(16) __nv_bfloat16 g_Ax [3 * AX_STRIDE];      // per-tower working A'
__device__ __align__(16) __nv_bfloat16 g_Ap [AX_STRIDE];          // pool-block output A'
__device__ __align__(16) float g_y[3 * Y_STRIDE];
__device__ __align__(16) float g_a[3 * Y_STRIDE];

// ---------------- PTX helpers (base sm_90 PTX only) ----------------
__device__ __forceinline__ uint32_t smem_u32(const void* p) {
    uint32_t a;
    asm("{ .reg .u64 t; cvta.to.shared.u64 t, %1; cvt.u32.u64 %0, t; }" : "=r"(a) : "l"(p));
    return a;
}
__device__ __forceinline__ void mbar_init(uint32_t a, uint32_t cnt) {
    asm volatile("mbarrier.init.shared.b64 [%0], %1;" :: "r"(a), "r"(cnt) : "memory");
}
__device__ __forceinline__ void mbar_expect_tx(uint32_t a, uint32_t bytes) {
    asm volatile("mbarrier.arrive.expect_tx.shared.b64 _, [%0], %1;" :: "r"(a), "r"(bytes) : "memory");
}
__device__ __forceinline__ void mbar_wait(uint32_t a, uint32_t parity) {
    asm volatile(
        "{\n\t.reg .pred P;\n\t"
        "WL_%=:\n\t"
        "mbarrier.try_wait.parity.acquire.cta.shared::cta.b64 P, [%0], %1, 0x989680;\n\t"
        "@!P bra WL_%=;\n\t}"
        :: "r"(a), "r"(parity) : "memory");
}
__device__ __forceinline__ void mbar_inval(uint32_t a) {
    asm volatile("mbarrier.inval.shared.b64 [%0];" :: "r"(a) : "memory");
}
__device__ __forceinline__ void bulk_g2s(uint32_t dst, const void* src, uint32_t bytes, uint32_t mbar) {
    asm volatile("cp.async.bulk.shared::cta.global.mbarrier::complete_tx::bytes [%0], [%1], %2, [%3];"
                 :: "r"(dst), "l"(src), "r"(bytes), "r"(mbar) : "memory");
}
__device__ __forceinline__ void ldsm4(uint32_t& r0, uint32_t& r1, uint32_t& r2, uint32_t& r3, uint32_t addr) {
    asm volatile("ldmatrix.sync.aligned.m8n8.x4.shared.b16 {%0,%1,%2,%3}, [%4];"
                 : "=r"(r0), "=r"(r1), "=r"(r2), "=r"(r3) : "r"(addr));
}
__device__ __forceinline__ void mma16816(float* c, const uint32_t* a, uint32_t b0, uint32_t b1) {
    asm volatile(
        "mma.sync.aligned.m16n8k16.row.col.f32.bf16.bf16.f32 "
        "{%0,%1,%2,%3}, {%4,%5,%6,%7}, {%8,%9}, {%0,%1,%2,%3};"
        : "+f"(c[0]), "+f"(c[1]), "+f"(c[2]), "+f"(c[3])
        : "r"(a[0]), "r"(a[1]), "r"(a[2]), "r"(a[3]), "r"(b0), "r"(b1));
}

#define SW128(o) ((o) ^ (((o) >> 3) & 0x70))

__device__ __forceinline__ void split8(const float* v, uint4& hi, uint4& lo) {
    __nv_bfloat16* hp = (__nv_bfloat16*)&hi;
    __nv_bfloat16* lp = (__nv_bfloat16*)&lo;
    #pragma unroll
    for (int i = 0; i < 8; ++i) {
        __nv_bfloat16 hb = __float2bfloat16(v[i]);
        hp[i] = hb;
        lp[i] = __float2bfloat16(v[i] - __bfloat162float(hb));
    }
}
// store an 8-value group into paired tile layout: tiles (mb,kt) -> [hi(16KB), lo(16KB)]
__device__ __forceinline__ void store_pair(__nv_bfloat16* base, int mb, int TK, int trow,
                                           int kprime, const uint4& hi, const uint4& lo) {
    int kt = kprime >> 6;
    int tcol = kprime & 63;
    uint32_t off = SW128((uint32_t)trow * 128u + (uint32_t)tcol * 2u);
    char* t0 = (char*)(base + (((size_t)(mb * TK + kt) * 2) << 13));
    *(uint4*)(t0 + off) = hi;
    *(uint4*)(t0 + 16384 + off) = lo;
}

// ---------------- ragged pooling -> pooler A' paired tiles (TK=32) ----------------
__global__ __launch_bounds__(128)
void pool_kernel(const float* __restrict__ h, const int* __restrict__ turns,
                 const int* __restrict__ parts, __nv_bfloat16* __restrict__ Abf) {
    int s = blockIdx.x;
    int b = s >> 4;
    int j = s & 15;
    int start = 1;
    #pragma unroll
    for (int t = 0; t < 16; ++t)
        if (t < j) start += parts[b * 16 + t];
    int count = parts[b * 16 + j];
    bool valid = (j < turns[b]);
    int c0 = threadIdx.x * 8;
    const float* base = h + ((size_t)b * SEQ + start) * DIM + c0;

    float mx[8], sm[8];
    #pragma unroll
    for (int i = 0; i < 8; ++i) { mx[i] = -CUDART_INF_F; sm[i] = 0.f; }
    if (valid) {
        int p = 0;
        for (; p + 1 < count; p += 2) {
            float4 v0 = *(const float4*)(base + (size_t)p * DIM);
            float4 v1 = *(const float4*)(base + (size_t)p * DIM + 4);
            float4 w0 = *(const float4*)(base + (size_t)(p + 1) * DIM);
            float4 w1 = *(const float4*)(base + (size_t)(p + 1) * DIM + 4);
            float v[8] = {v0.x, v0.y, v0.z, v0.w, v1.x, v1.y, v1.z, v1.w};
            float w[8] = {w0.x, w0.y, w0.z, w0.w, w1.x, w1.y, w1.z, w1.w};
            #pragma unroll
            for (int i = 0; i < 8; ++i) {
                mx[i] = fmaxf(mx[i], fmaxf(v[i], w[i]));
                sm[i] += v[i] + w[i];
            }
        }
        if (p < count) {
            float4 v0 = *(const float4*)(base + (size_t)p * DIM);
            float4 v1 = *(const float4*)(base + (size_t)p * DIM + 4);
            float v[8] = {v0.x, v0.y, v0.z, v0.w, v1.x, v1.y, v1.z, v1.w};
            #pragma unroll
            for (int i = 0; i < 8; ++i) { mx[i] = fmaxf(mx[i], v[i]); sm[i] += v[i]; }
        }
        float inv = 1.0f / (float)count;
        #pragma unroll
        for (int i = 0; i < 8; ++i) sm[i] *= inv;
    } else {
        #pragma unroll
        for (int i = 0; i < 8; ++i) sm[i] = CUDART_NAN_F;
    }
    int mb = s >> 7, trow = s & 127;
    uint4 hi, lo;
    split8(mx, hi, lo);
    store_pair(Abf, mb, 32, trow, c0, hi, lo);
    split8(sm, hi, lo);
    store_pair(Abf, mb, 32, trow, 1024 + c0, hi, lo);
}

// ---------------- weight conversion body ----------------
__device__ __forceinline__ void wconv_body(const float* __restrict__ W, __nv_bfloat16* __restrict__ dst,
                                           int nb, int kt, int TK) {
    __shared__ float sh[64][129];
    int k0 = kt * 64;
    int tid = threadIdx.x;
    for (int idx = tid; idx < 2048; idx += 256) {
        int row = idx >> 5, c4 = (idx & 31) * 4;
        float4 v = *(const float4*)&W[(size_t)(k0 + row) * 1024 + nb * 128 + c4];
        sh[row][c4] = v.x; sh[row][c4 + 1] = v.y; sh[row][c4 + 2] = v.z; sh[row][c4 + 3] = v.w;
    }
    __syncthreads();
    int n = tid >> 1, kc0 = (tid & 1) * 32;
    char* t0 = (char*)(dst + (((size_t)(nb * TK + kt) * 2) << 13));
    #pragma unroll
    for (int g = 0; g < 4; ++g) {
        uint4 h4, l4;
        __nv_bfloat16* hp = (__nv_bfloat16*)&h4;
        __nv_bfloat16* lp = (__nv_bfloat16*)&l4;
        #pragma unroll
        for (int i = 0; i < 8; ++i) {
            float v = sh[kc0 + g * 8 + i][n];
            __nv_bfloat16 hb = __float2bfloat16(v);
            hp[i] = hb;
            lp[i] = __float2bfloat16(v - __bfloat162float(hb));
        }
        uint32_t off = SW128((uint32_t)n * 128u + (uint32_t)(kc0 + g * 8) * 2u);
        *(uint4*)(t0 + off) = h4;
        *(uint4*)(t0 + 16384 + off) = l4;
    }
}

__global__ __launch_bounds__(256)
void wconv_pooler(const float* __restrict__ W, __nv_bfloat16* __restrict__ dst) {
    wconv_body(W, dst, blockIdx.x, blockIdx.y, 32);
}
__global__ __launch_bounds__(256)
void wconv_all(const float* __restrict__ pool_W, const float* __restrict__ emo_Ws,
               const float* __restrict__ act_Ws, const float* __restrict__ int_Ws,
               __nv_bfloat16* __restrict__ wl) {
    int z = blockIdx.z;
    const float* W;
    if (z == 0) W = pool_W;
    else {
        int t = (z - 1) >> 2, k = (z - 1) & 3;
        const float* Ws = (t == 0) ? emo_Ws : (t == 1) ? act_Ws : int_Ws;
        W = Ws + (size_t)k * DIM * DIM;
    }
    wconv_body(W, wl + (size_t)z * LAYER_W_ELEMS, blockIdx.x, blockIdx.y, 16);
}

// ---------------- HMMA bf16x3 GEMM (R8 schedule) with generalized z/mb strides ----------------
// CTA 128(M) x 64(N); grid (16 nb-half, 8 mb, nz). Stage = {Ah,Al,Wh,Wl} = 48KB, NSTAGE=2.
// Warp tile 32(M) x 32(N), 4m x 2n warps, per-i register-pipelined prefetch.
// z dim can be a batch index (az/wz select operand slices) OR a split-K index
// (az/wz select K-halves and Y halves via yz).
#define NSTAGE 2
#define STAGE_BYTES 49152
__global__ __launch_bounds__(256, 2)
void mma_gemm(const __nv_bfloat16* __restrict__ Ab, size_t az, size_t amb,
              const __nv_bfloat16* __restrict__ Wb, size_t wz, size_t wnb,
              float* __restrict__ Yb, size_t yz, int TK) {
    extern __shared__ char smem[];
    uint32_t base = smem_u32(smem);
    uint32_t tbase = (base + 1023u) & ~1023u;
    uint32_t ctrl = tbase + NSTAGE * STAGE_BYTES;

    int tid = threadIdx.x;
    int wid = tid >> 5, lane = tid & 31;
    int wm = (wid & 3) * 32;     // 4 m-warps
    int wn = (wid >> 2) * 32;    // 2 n-warps
    int z = blockIdx.z;

    if (tid == 0) { mbar_init(ctrl, 1); mbar_init(ctrl + 8, 1); }
    __syncthreads();

    const char* Aptr = (const char*)(Ab + (size_t)z * az) + (size_t)blockIdx.y * amb;
    const char* Wptr = (const char*)(Wb + (size_t)z * wz) + (size_t)(blockIdx.x >> 1) * wnb;
    uint32_t bhalf = (blockIdx.x & 1) * 8192u;

    if (tid == 0) {
        #pragma unroll
        for (int i = 0; i < NSTAGE; ++i) {
            uint32_t mb = ctrl + i * 8;
            mbar_expect_tx(mb, STAGE_BYTES);
            bulk_g2s(tbase + i * STAGE_BYTES,         Aptr + (size_t)i * 32768, 32768u, mb);
            bulk_g2s(tbase + i * STAGE_BYTES + 32768, Wptr + (size_t)i * 32768 + bhalf, 8192u, mb);
            bulk_g2s(tbase + i * STAGE_BYTES + 40960, Wptr + (size_t)i * 32768 + 16384 + bhalf, 8192u, mb);
        }
    }

    int rA[2], xA[2];
    #pragma unroll
    for (int i = 0; i < 2; ++i) {
        int row = wm + i * 16 + (lane & 15);
        rA[i] = row * 128;
        xA[i] = (row & 7) << 4;
    }
    int hiA = (lane >> 4) << 4;
    int rowB = wn + (lane & 7) + ((lane >> 4) << 3);
    int rB = rowB * 128;                 // group 0; group 1 at +16 rows = +2048B
    int xB = (rowB & 7) << 4;
    int hiB = ((lane >> 3) & 1) << 4;

    float acc[2][4][4];
    #pragma unroll
    for (int i = 0; i < 2; ++i)
        #pragma unroll
        for (int j = 0; j < 4; ++j)
            #pragma unroll
            for (int q = 0; q < 4; ++q) acc[i][j][q] = 0.f;

    for (int kt = 0; kt < TK; ++kt) {
        int s = kt & 1;
        mbar_wait(ctrl + s * 8, (kt >> 1) & 1);
        uint32_t sAh = tbase + s * STAGE_BYTES;
        uint32_t sAl = sAh + 16384u;
        uint32_t sWh = sAh + 32768u;
        uint32_t sWl = sAh + 40960u;

        uint32_t ah[2][4], al[2][4], wh[2][8], wl[2][8];
        // preload kk=0: B both col-groups, A i=0
        {
            uint32_t boff = (uint32_t)hiB ^ (uint32_t)xB;
            ldsm4(wh[0][0], wh[0][1], wh[0][2], wh[0][3], sWh + rB + boff);
            ldsm4(wh[0][4], wh[0][5], wh[0][6], wh[0][7], sWh + rB + 2048 + boff);
            ldsm4(wl[0][0], wl[0][1], wl[0][2], wl[0][3], sWl + rB + boff);
            ldsm4(wl[0][4], wl[0][5], wl[0][6], wl[0][7], sWl + rB + 2048 + boff);
            uint32_t aoff = (uint32_t)hiA ^ (uint32_t)xA[0];
            ldsm4(ah[0][0], ah[0][1], ah[0][2], ah[0][3], sAh + rA[0] + aoff);
            ldsm4(al[0][0], al[0][1], al[0][2], al[0][3], sAl + rA[0] + aoff);
        }
        #pragma unroll
        for (int kk = 0; kk < 4; ++kk) {
            const int bb = kk & 1;
            #pragma unroll
            for (int i = 0; i < 2; ++i) {
                const int ab = (kk * 2 + i) & 1;
                if (i == 0) {
                    uint32_t aoff = (uint32_t)((kk << 5) + hiA) ^ (uint32_t)xA[1];
                    ldsm4(ah[ab ^ 1][0], ah[ab ^ 1][1], ah[ab ^ 1][2], ah[ab ^ 1][3], sAh + rA[1] + aoff);
                    ldsm4(al[ab ^ 1][0], al[ab ^ 1][1], al[ab ^ 1][2], al[ab ^ 1][3], sAl + rA[1] + aoff);
                } else if (kk < 3) {
                    uint32_t boff = (uint32_t)(((kk + 1) << 5) + hiB) ^ (uint32_t)xB;
                    ldsm4(wh[bb ^ 1][0], wh[bb ^ 1][1], wh[bb ^ 1][2], wh[bb ^ 1][3], sWh + rB + boff);
                    ldsm4(wh[bb ^ 1][4], wh[bb ^ 1][5], wh[bb ^ 1][6], wh[bb ^ 1][7], sWh + rB + 2048 + boff);
                    ldsm4(wl[bb ^ 1][0], wl[bb ^ 1][1], wl[bb ^ 1][2], wl[bb ^ 1][3], sWl + rB + boff);
                    ldsm4(wl[bb ^ 1][4], wl[bb ^ 1][5], wl[bb ^ 1][6], wl[bb ^ 1][7], sWl + rB + 2048 + boff);
                    uint32_t aoff = (uint32_t)(((kk + 1) << 5) + hiA) ^ (uint32_t)xA[0];
                    ldsm4(ah[ab ^ 1][0], ah[ab ^ 1][1], ah[ab ^ 1][2], ah[ab ^ 1][3], sAh + rA[0] + aoff);
                    ldsm4(al[ab ^ 1][0], al[ab ^ 1][1], al[ab ^ 1][2], al[ab ^ 1][3], sAl + rA[0] + aoff);
                }
                mma16816(acc[i][0], ah[ab], wh[bb][0], wh[bb][1]);
                mma16816(acc[i][1], ah[ab], wh[bb][2], wh[bb][3]);
                mma16816(acc[i][2], ah[ab], wh[bb][4], wh[bb][5]);
                mma16816(acc[i][3], ah[ab], wh[bb][6], wh[bb][7]);
                mma16816(acc[i][0], ah[ab], wl[bb][0], wl[bb][1]);
                mma16816(acc[i][1], ah[ab], wl[bb][2], wl[bb][3]);
                mma16816(acc[i][2], ah[ab], wl[bb][4], wl[bb][5]);
                mma16816(acc[i][3], ah[ab], wl[bb][6], wl[bb][7]);
                mma16816(acc[i][0], al[ab], wh[bb][0], wh[bb][1]);
                mma16816(acc[i][1], al[ab], wh[bb][2], wh[bb][3]);
                mma16816(acc[i][2], al[ab], wh[bb][4], wh[bb][5]);
                mma16816(acc[i][3], al[ab], wh[bb][6], wh[bb][7]);
            }
        }
        __syncthreads();
        if (tid == 0 && kt + NSTAGE < TK) {
            int nk = kt + NSTAGE;
            uint32_t mb = ctrl + s * 8;
            mbar_expect_tx(mb, STAGE_BYTES);
            bulk_g2s(sAh,          Aptr + (size_t)nk * 32768, 32768u, mb);
            bulk_g2s(sAh + 32768u, Wptr + (size_t)nk * 32768 + bhalf, 8192u, mb);
            bulk_g2s(sAh + 40960u, Wptr + (size_t)nk * 32768 + 16384 + bhalf, 8192u, mb);
        }
    }

    float* Y = Yb + (size_t)z * yz;
    int r0 = blockIdx.y * 128 + wm + (lane >> 2);
    #pragma unroll
    for (int i = 0; i < 2; ++i) {
        #pragma unroll
        for (int j = 0; j < 4; ++j) {
            int row = r0 + i * 16;
            int col = blockIdx.x * 64 + wn + j * 8 + ((lane & 3) << 1);
            *(float2*)&Y[(size_t)row * 1024 + col]       = make_float2(acc[i][j][0], acc[i][j][1]);
            *(float2*)&Y[(size_t)(row + 8) * 1024 + col] = make_float2(acc[i][j][2], acc[i][j][3]);
        }
    }
    __syncthreads();
    if (tid == 0) { mbar_inval(ctrl); mbar_inval(ctrl + 8); }
}

// ---------------- split-K combine: tanh(y0 + y1 + bias) -> A' tiles (TK=16) ----------------
__global__ __launch_bounds__(256)
void act2_kernel(const float* __restrict__ y0, const float* __restrict__ y1,
                 const float* __restrict__ bias, __nv_bfloat16* __restrict__ Aout) {
    int c0 = blockIdx.x * 8;
    float bv[8];
    #pragma unroll
    for (int i = 0; i < 8; ++i) bv[i] = bias[c0 + i];
    for (int r = threadIdx.x; r < 1024; r += 256) {
        float4 a0 = *(const float4*)&y0[(size_t)r * 1024 + c0];
        float4 a1 = *(const float4*)&y0[(size_t)r * 1024 + c0 + 4];
        float4 b0 = *(const float4*)&y1[(size_t)r * 1024 + c0];
        float4 b1 = *(const float4*)&y1[(size_t)r * 1024 + c0 + 4];
        float v[8] = {a0.x + b0.x, a0.y + b0.y, a0.z + b0.z, a0.w + b0.w,
                      a1.x + b1.x, a1.y + b1.y, a1.z + b1.z, a1.w + b1.w};
        #pragma unroll
        for (int i = 0; i < 8; ++i) v[i] = tanhf(v[i] + bv[i]);
        uint4 hi, lo;
        split8(v, hi, lo);
        store_pair(Aout, r >> 7, 16, r & 127, c0, hi, lo);
    }
}

// ---------------- BatchNorm(+tanh), batched over z; optional split-K input sum ----------------
template <bool TILES, bool FP32, bool SPLIT>
__global__ __launch_bounds__(256)
void bn_kernel(const float* __restrict__ Yb, const float* __restrict__ Yb2, size_t yz,
               const float* __restrict__ g0, const float* __restrict__ g1, const float* __restrict__ g2,
               const float* __restrict__ be0, const float* __restrict__ be1, const float* __restrict__ be2,
               float* __restrict__ afpB, size_t afz,
               __nv_bfloat16* __restrict__ AtB, size_t atz) {
    __shared__ float ss[32][8], sq[32][8];
    __shared__ float sscale[8], sshift[8];
    int z = blockIdx.y;
    const float* Y  = Yb + (size_t)z * yz;
    const float* Y2 = SPLIT ? (Yb2 + (size_t)z * yz) : nullptr;
    const float* g    = (z == 0) ? g0 : (z == 1) ? g1 : g2;
    const float* beta = (z == 0) ? be0 : (z == 1) ? be1 : be2;
    int tid = threadIdx.x;
    int c0 = blockIdx.x * 8;
    int c = tid & 7, rg = tid >> 3;
    float s = 0.f, q = 0.f;
    for (int r = rg; r < 1024; r += 32) {
        float v = Y[(size_t)r * 1024 + c0 + c];
        if (SPLIT) v += Y2[(size_t)r * 1024 + c0 + c];
        s += v; q += v * v;
    }
    ss[rg][c] = s; sq[rg][c] = q;
    __syncthreads();
    if (tid < 8) {
        float ts = 0.f, tq = 0.f;
        #pragma unroll
        for (int i = 0; i < 32; ++i) { ts += ss[i][tid]; tq += sq[i][tid]; }
        float mean = ts * (1.f / 1024.f);
        float var  = fmaxf(tq * (1.f / 1024.f) - mean * mean, 0.f);
        float rs   = rsqrtf(var + 1e-5f);
        float sc   = g[c0 + tid] * rs;
        sscale[tid] = sc;
        sshift[tid] = beta[c0 + tid] - mean * sc;
    }
    __syncthreads();
    float sc[8], sh[8];
    #pragma unroll
    for (int i = 0; i < 8; ++i) { sc[i] = sscale[i]; sh[i] = sshift[i]; }
    float* afp = FP32 ? (afpB + (size_t)z * afz) : nullptr;
    __nv_bfloat16* At = TILES ? (AtB + (size_t)z * atz) : nullptr;
    for (int r = tid; r < 1024; r += 256) {
        float4 v0 = *(const float4*)&Y[(size_t)r * 1024 + c0];
        float4 v1 = *(const float4*)&Y[(size_t)r * 1024 + c0 + 4];
        float v[8] = {v0.x, v0.y, v0.z, v0.w, v1.x, v1.y, v1.z, v1.w};
        if (SPLIT) {
            float4 u0 = *(const float4*)&Y2[(size_t)r * 1024 + c0];
            float4 u1 = *(const float4*)&Y2[(size_t)r * 1024 + c0 + 4];
            v[0] += u0.x; v[1] += u0.y; v[2] += u0.z; v[3] += u0.w;
            v[4] += u1.x; v[5] += u1.y; v[6] += u1.z; v[7] += u1.w;
        }
        #pragma unroll
        for (int i = 0; i < 8; ++i) v[i] = tanhf(v[i] * sc[i] + sh[i]);
        if (FP32) {
            *(float4*)&afp[(size_t)r * 1024 + c0]     = make_float4(v[0], v[1], v[2], v[3]);
            *(float4*)&afp[(size_t)r * 1024 + c0 + 4] = make_float4(v[4], v[5], v[6], v[7]);
        }
        if (TILES) {
            uint4 hi, lo;
            split8(v, hi, lo);
            store_pair(At, r >> 7, 16, r & 127, c0, hi, lo);
        }
    }
}

// ---------------- batched head GEMMs: grid (128, 3) ----------------
__global__ __launch_bounds__(128)
void final_kernel(const float* __restrict__ Xb, size_t xz,
                  const float* __restrict__ wf0, const float* __restrict__ wf1, const float* __restrict__ wf2,
                  const float* __restrict__ bf0, const float* __restrict__ bf1, const float* __restrict__ bf2,
                  float* __restrict__ outb) {
    __shared__ float sh[8][1024];
    int t = blockIdx.y;
    const int nout = (t == 0) ? 7 : (t == 1) ? 5 : 102;
    const int off  = (t == 0) ? 0 : (t == 1) ? 7 * NSEG : 12 * NSEG;
    const float* X  = Xb + (size_t)t * xz;
    const float* Wf = (t == 0) ? wf0 : (t == 1) ? wf1 : wf2;
    const float* bf = (t == 0) ? bf0 : (t == 1) ? bf1 : bf2;
    float* out = outb + off;

    int r0 = blockIdx.x * 8;
    const float4* Xs = (const float4*)(X + (size_t)r0 * 1024);
    #pragma unroll
    for (int q = 0; q < 16; ++q) {
        int i = threadIdx.x + q * 128;
        int row = i >> 8, col4 = (i & 255);
        *(float4*)&sh[row][col4 * 4] = Xs[(size_t)row * 256 + col4];
    }
    __syncthreads();
    for (int n = threadIdx.x; n < nout; n += 128) {
        float acc[8];
        float bv = bf[n];
        #pragma unroll
        for (int r = 0; r < 8; ++r) acc[r] = bv;
        #pragma unroll 8
        for (int k = 0; k < 1024; ++k) {
            float w = Wf[(size_t)k * nout + n];
            #pragma unroll
            for (int r = 0; r < 8; ++r) acc[r] += sh[r][k] * w;
        }
        #pragma unroll
        for (int r = 0; r < 8; ++r)
            out[(size_t)(r0 + r) * nout + n] = acc[r];
    }
}

// ---------------- launch ----------------
#define GEMM_SMEM (NSTAGE * STAGE_BYTES + 1024 + 64)

extern "C" void kernel_launch(void* const* d_in, const int* in_sizes, int n_in,
                              void* d_out, int out_size) {
    const float* h        = (const float*)d_in[0];
    const int*   turns    = (const int*)  d_in[1];
    const int*   parts    = (const int*)  d_in[2];
    const float* pooler_W = (const float*)d_in[3];
    const float* pooler_b = (const float*)d_in[4];
    const float* pool_W   = (const float*)d_in[5];
    // d_in[6] pool_b: cancelled by BN mean subtraction
    const float* pool_g   = (const float*)d_in[7];
    const float* pool_be  = (const float*)d_in[8];
    const float* emo_Ws   = (const float*)d_in[9];
    const float* emo_gs   = (const float*)d_in[11];
    const float* emo_be   = (const float*)d_in[12];
    const float* emo_Wf   = (const float*)d_in[13];
    const float* emo_bf   = (const float*)d_in[14];
    const float* act_Ws   = (const float*)d_in[15];
    const float* act_gs   = (const float*)d_in[17];
    const float* act_be   = (const float*)d_in[18];
    const float* act_Wf   = (const float*)d_in[19];
    const float* act_bf   = (const float*)d_in[20];
    const float* int_Ws   = (const float*)d_in[21];
    const float* int_gs   = (const float*)d_in[23];
    const float* int_be   = (const float*)d_in[24];
    const float* int_Wf   = (const float*)d_in[25];
    const float* int_bf   = (const float*)d_in[26];
    float* out = (float*)d_out;

    __nv_bfloat16 *Wbf, *Abf, *Ax, *Ap;
    float *y, *a;
    cudaGetSymbolAddress((void**)&Wbf, g_Wbf);
    cudaGetSymbolAddress((void**)&Abf, g_Abf);
    cudaGetSymbolAddress((void**)&Ax,  g_Ax);
    cudaGetSymbolAddress((void**)&Ap,  g_Ap);
    cudaGetSymbolAddress((void**)&y,   g_y);
    cudaGetSymbolAddress((void**)&a,   g_a);
    __nv_bfloat16* wl = Wbf + POOLER_W_ELEMS;

    cudaFuncSetAttribute(mma_gemm, cudaFuncAttributeMaxDynamicSharedMemorySize, GEMM_SMEM);

    // weights: 2 launches
    wconv_pooler<<<dim3(8, 32), 256>>>(pooler_W, Wbf);
    wconv_all<<<dim3(8, 16, 13), 256>>>(pool_W, emo_Ws, act_Ws, int_Ws, wl);

    // pooling
    pool_kernel<<<NSEG, 128>>>(h, turns, parts, Abf);

    // pooler GEMM, split-K=2 (z = K-half): halves into g_y[0], g_y[1]
    mma_gemm<<<dim3(16, 8, 2), 256, GEMM_SMEM>>>(
        Abf, (size_t)16 * 2 * 8192, (size_t)32 * 32768,
        Wbf, (size_t)16 * 2 * 8192, (size_t)32 * 32768,
        y, Y_STRIDE, 16);
    act2_kernel<<<128, 256>>>(y, y + Y_STRIDE, pooler_b, Ax);

    // pool Linear_Block, split-K=2 -> bn sums halves -> Ap
    mma_gemm<<<dim3(16, 8, 2), 256, GEMM_SMEM>>>(
        Ax, (size_t)8 * 2 * 8192, (size_t)16 * 32768,
        wl, (size_t)8 * 2 * 8192, (size_t)16 * 32768,
        y, Y_STRIDE, 8);
    bn_kernel<true, false, true><<<dim3(128, 1), 256>>>(
        y, y + Y_STRIDE, 0,
        pool_g, pool_g, pool_g, pool_be, pool_be, pool_be,
        nullptr, 0, Ap, 0);

    // tower depths, batched over the 3 towers (z = tower)
    for (int k = 0; k < 4; ++k) {
        const __nv_bfloat16* Ain = (k == 0) ? Ap : Ax;
        size_t az = (k == 0) ? 0 : (size_t)AX_STRIDE;
        mma_gemm<<<dim3(16, 8, 3), 256, GEMM_SMEM>>>(
            Ain, az, (size_t)16 * 32768,
            wl + (size_t)(1 + k) * LAYER_W_ELEMS, (size_t)4 * LAYER_W_ELEMS, (size_t)16 * 32768,
            y, Y_STRIDE, 16);
        if (k < 3)
            bn_kernel<true, false, false><<<dim3(128, 3), 256>>>(
                y, nullptr, Y_STRIDE,
                emo_gs + k * DIM, act_gs + k * DIM, int_gs + k * DIM,
                emo_be + k * DIM, act_be + k * DIM, int_be + k * DIM,
                nullptr, 0, Ax, AX_STRIDE);
        else
            bn_kernel<false, true, false><<<dim3(128, 3), 256>>>(
                y, nullptr, Y_STRIDE,
                emo_gs + k * DIM, act_gs + k * DIM, int_gs + k * DIM,
                emo_be + k * DIM, act_be + k * DIM, int_be + k * DIM,
                a, Y_STRIDE, nullptr, 0);
    }

    // batched heads
    final_kernel<<<dim3(128, 3), 128>>>(a, Y_STRIDE, emo_Wf, act_Wf, int_Wf,
                                        emo_bf, act_bf, int_bf, out);
}

// round 11
// speedup vs baseline: 1.4609x; 1.0385x over previous
#include <cuda_runtime.h>
#include <cuda_bf16.h>
#include <math_constants.h>
#include <cstdint>
#include <cstddef>

#define DIM 1024
#define NSEG 1024
#define SEQ 2048

// tile = 128 rows x 64 bf16 cols (16KB), SW128. Pairs [hi,lo] stored adjacently.
#define LAYER_W_ELEMS  (8 * 16 * 2 * 8192)   // 8 nb x 16 kt x {hi,lo}
#define POOLER_W_ELEMS (8 * 32 * 2 * 8192)
#define AX_STRIDE      (8 * 16 * 2 * 8192)   // per-tower A' buffer (4MB)
#define Y_STRIDE       (NSEG * DIM)

__device__ __align__(16) __nv_bfloat16 g_Wbf[POOLER_W_ELEMS + 13 * LAYER_W_ELEMS];
__device__ __align__(16) __nv_bfloat16 g_Abf[8 * 32 * 2 * 8192];  // pooler A'
__device__ __align__(16) __nv_bfloat16 g_Ax [3 * AX_STRIDE];      // per-tower working A'
__device__ __align__(16) __nv_bfloat16 g_Ap [AX_STRIDE];          // pool-block output A'
__device__ __align__(16) float g_y[3 * Y_STRIDE];
__device__ __align__(16) float g_a[3 * Y_STRIDE];

// ---------------- PTX helpers (base sm_90 PTX only) ----------------
__device__ __forceinline__ uint32_t smem_u32(const void* p) {
    uint32_t a;
    asm("{ .reg .u64 t; cvta.to.shared.u64 t, %1; cvt.u32.u64 %0, t; }" : "=r"(a) : "l"(p));
    return a;
}
__device__ __forceinline__ void mbar_init(uint32_t a, uint32_t cnt) {
    asm volatile("mbarrier.init.shared.b64 [%0], %1;" :: "r"(a), "r"(cnt) : "memory");
}
__device__ __forceinline__ void mbar_expect_tx(uint32_t a, uint32_t bytes) {
    asm volatile("mbarrier.arrive.expect_tx.shared.b64 _, [%0], %1;" :: "r"(a), "r"(bytes) : "memory");
}
__device__ __forceinline__ void mbar_wait(uint32_t a, uint32_t parity) {
    asm volatile(
        "{\n\t.reg .pred P;\n\t"
        "WL_%=:\n\t"
        "mbarrier.try_wait.parity.acquire.cta.shared::cta.b64 P, [%0], %1, 0x989680;\n\t"
        "@!P bra WL_%=;\n\t}"
        :: "r"(a), "r"(parity) : "memory");
}
__device__ __forceinline__ void mbar_inval(uint32_t a) {
    asm volatile("mbarrier.inval.shared.b64 [%0];" :: "r"(a) : "memory");
}
__device__ __forceinline__ void bulk_g2s(uint32_t dst, const void* src, uint32_t bytes, uint32_t mbar) {
    asm volatile("cp.async.bulk.shared::cta.global.mbarrier::complete_tx::bytes [%0], [%1], %2, [%3];"
                 :: "r"(dst), "l"(src), "r"(bytes), "r"(mbar) : "memory");
}
__device__ __forceinline__ void ldsm4(uint32_t& r0, uint32_t& r1, uint32_t& r2, uint32_t& r3, uint32_t addr) {
    asm volatile("ldmatrix.sync.aligned.m8n8.x4.shared.b16 {%0,%1,%2,%3}, [%4];"
                 : "=r"(r0), "=r"(r1), "=r"(r2), "=r"(r3) : "r"(addr));
}
__device__ __forceinline__ void mma16816(float* c, const uint32_t* a, uint32_t b0, uint32_t b1) {
    asm volatile(
        "mma.sync.aligned.m16n8k16.row.col.f32.bf16.bf16.f32 "
        "{%0,%1,%2,%3}, {%4,%5,%6,%7}, {%8,%9}, {%0,%1,%2,%3};"
        : "+f"(c[0]), "+f"(c[1]), "+f"(c[2]), "+f"(c[3])
        : "r"(a[0]), "r"(a[1]), "r"(a[2]), "r"(a[3]), "r"(b0), "r"(b1));
}

#define SW128(o) ((o) ^ (((o) >> 3) & 0x70))

__device__ __forceinline__ void split8(const float* v, uint4& hi, uint4& lo) {
    __nv_bfloat16* hp = (__nv_bfloat16*)&hi;
    __nv_bfloat16* lp = (__nv_bfloat16*)&lo;
    #pragma unroll
    for (int i = 0; i < 8; ++i) {
        __nv_bfloat16 hb = __float2bfloat16(v[i]);
        hp[i] = hb;
        lp[i] = __float2bfloat16(v[i] - __bfloat162float(hb));
    }
}
// store an 8-value group into paired tile layout: tiles (mb,kt) -> [hi(16KB), lo(16KB)]
__device__ __forceinline__ void store_pair(__nv_bfloat16* base, int mb, int TK, int trow,
                                           int kprime, const uint4& hi, const uint4& lo) {
    int kt = kprime >> 6;
    int tcol = kprime & 63;
    uint32_t off = SW128((uint32_t)trow * 128u + (uint32_t)tcol * 2u);
    char* t0 = (char*)(base + (((size_t)(mb * TK + kt) * 2) << 13));
    *(uint4*)(t0 + off) = hi;
    *(uint4*)(t0 + 16384 + off) = lo;
}
// store a 4-value group (8B, SW128-safe) into paired tile layout
__device__ __forceinline__ void store_pair4(__nv_bfloat16* base, int mb, int TK, int trow,
                                            int kprime, const float* v) {
    int kt = kprime >> 6;
    int tcol = kprime & 63;
    uint32_t off = SW128((uint32_t)trow * 128u + (uint32_t)tcol * 2u);
    char* t0 = (char*)(base + (((size_t)(mb * TK + kt) * 2) << 13));
    __nv_bfloat16 h[4], l[4];
    #pragma unroll
    for (int i = 0; i < 4; ++i) {
        h[i] = __float2bfloat16(v[i]);
        l[i] = __float2bfloat16(v[i] - __bfloat162float(h[i]));
    }
    *(uint2*)(t0 + off)         = *(uint2*)h;
    *(uint2*)(t0 + 16384 + off) = *(uint2*)l;
}
// store 2 adjacent values (4B) into paired tile layout (SW128 keeps 4B alignment)
__device__ __forceinline__ void store_pair2(__nv_bfloat16* base, int mb, int TK, int trow,
                                            int col, float v0, float v1) {
    int kt = col >> 6;
    int tcol = col & 63;
    uint32_t off = SW128((uint32_t)trow * 128u + (uint32_t)tcol * 2u);
    char* t0 = (char*)(base + (((size_t)(mb * TK + kt) * 2) << 13));
    __nv_bfloat16 h0 = __float2bfloat16(v0);
    __nv_bfloat16 h1 = __float2bfloat16(v1);
    __nv_bfloat16 l0 = __float2bfloat16(v0 - __bfloat162float(h0));
    __nv_bfloat16 l1 = __float2bfloat16(v1 - __bfloat162float(h1));
    __nv_bfloat162 hw = __halves2bfloat162(h0, h1);
    __nv_bfloat162 lw = __halves2bfloat162(l0, l1);
    *(__nv_bfloat162*)(t0 + off) = hw;
    *(__nv_bfloat162*)(t0 + 16384 + off) = lw;
}

// ---------------- weight conversion body (256 threads) ----------------
__device__ __forceinline__ void wconv_body(const float* __restrict__ W, __nv_bfloat16* __restrict__ dst,
                                           int nb, int kt, int TK) {
    __shared__ float sh[64][129];
    int k0 = kt * 64;
    int tid = threadIdx.x;
    for (int idx = tid; idx < 2048; idx += 256) {
        int row = idx >> 5, c4 = (idx & 31) * 4;
        float4 v = *(const float4*)&W[(size_t)(k0 + row) * 1024 + nb * 128 + c4];
        sh[row][c4] = v.x; sh[row][c4 + 1] = v.y; sh[row][c4 + 2] = v.z; sh[row][c4 + 3] = v.w;
    }
    __syncthreads();
    int n = tid >> 1, kc0 = (tid & 1) * 32;
    char* t0 = (char*)(dst + (((size_t)(nb * TK + kt) * 2) << 13));
    #pragma unroll
    for (int g = 0; g < 4; ++g) {
        uint4 h4, l4;
        __nv_bfloat16* hp = (__nv_bfloat16*)&h4;
        __nv_bfloat16* lp = (__nv_bfloat16*)&l4;
        #pragma unroll
        for (int i = 0; i < 8; ++i) {
            float v = sh[kc0 + g * 8 + i][n];
            __nv_bfloat16 hb = __float2bfloat16(v);
            hp[i] = hb;
            lp[i] = __float2bfloat16(v - __bfloat162float(hb));
        }
        uint32_t off = SW128((uint32_t)n * 128u + (uint32_t)(kc0 + g * 8) * 2u);
        *(uint4*)(t0 + off) = h4;
        *(uint4*)(t0 + 16384 + off) = l4;
    }
}

// ---------------- ragged pooling body (256 threads, 4 dims/thread) ----------------
__device__ __forceinline__ void pool_body(const float* __restrict__ h, const int* __restrict__ turns,
                                          const int* __restrict__ parts, __nv_bfloat16* __restrict__ Abf,
                                          int s) {
    int b = s >> 4;
    int j = s & 15;
    int start = 1;
    #pragma unroll
    for (int t = 0; t < 16; ++t)
        if (t < j) start += parts[b * 16 + t];
    int count = parts[b * 16 + j];
    bool valid = (j < turns[b]);
    int c0 = threadIdx.x * 4;
    const float* base = h + ((size_t)b * SEQ + start) * DIM + c0;

    float mx[4], sm[4];
    #pragma unroll
    for (int i = 0; i < 4; ++i) { mx[i] = -CUDART_INF_F; sm[i] = 0.f; }
    if (valid) {
        int p = 0;
        for (; p + 1 < count; p += 2) {
            float4 v0 = *(const float4*)(base + (size_t)p * DIM);
            float4 w0 = *(const float4*)(base + (size_t)(p + 1) * DIM);
            float v[4] = {v0.x, v0.y, v0.z, v0.w};
            float w[4] = {w0.x, w0.y, w0.z, w0.w};
            #pragma unroll
            for (int i = 0; i < 4; ++i) {
                mx[i] = fmaxf(mx[i], fmaxf(v[i], w[i]));
                sm[i] += v[i] + w[i];
            }
        }
        if (p < count) {
            float4 v0 = *(const float4*)(base + (size_t)p * DIM);
            float v[4] = {v0.x, v0.y, v0.z, v0.w};
            #pragma unroll
            for (int i = 0; i < 4; ++i) { mx[i] = fmaxf(mx[i], v[i]); sm[i] += v[i]; }
        }
        float inv = 1.0f / (float)count;
        #pragma unroll
        for (int i = 0; i < 4; ++i) sm[i] *= inv;
    } else {
        #pragma unroll
        for (int i = 0; i < 4; ++i) sm[i] = CUDART_NAN_F;
    }
    int mb = s >> 7, trow = s & 127;
    store_pair4(Abf, mb, 32, trow, c0, mx);
    store_pair4(Abf, mb, 32, trow, 1024 + c0, sm);
}

// ---------------- merged prep: pool + all weight conversions, one launch ----------------
// grid: [0,1024) pool segments | [1024,1280) pooler wconv | [1280,2944) 13 layer wconvs
__global__ __launch_bounds__(256)
void prep_kernel(const float* __restrict__ h, const int* __restrict__ turns,
                 const int* __restrict__ parts, __nv_bfloat16* __restrict__ Abf,
                 const float* __restrict__ pooler_W, __nv_bfloat16* __restrict__ Wpool,
                 const float* __restrict__ pool_W, const float* __restrict__ emo_Ws,
                 const float* __restrict__ act_Ws, const float* __restrict__ int_Ws,
                 __nv_bfloat16* __restrict__ wl) {
    int bid = blockIdx.x;
    if (bid < 1024) {
        pool_body(h, turns, parts, Abf, bid);
    } else if (bid < 1280) {
        int idx = bid - 1024;
        wconv_body(pooler_W, Wpool, idx & 7, idx >> 3, 32);
    } else {
        int idx = bid - 1280;
        int layer = idx >> 7;
        int rem = idx & 127;
        const float* W;
        if (layer == 0) W = pool_W;
        else {
            int t = (layer - 1) >> 2, k = (layer - 1) & 3;
            const float* Ws = (t == 0) ? emo_Ws : (t == 1) ? act_Ws : int_Ws;
            W = Ws + (size_t)k * DIM * DIM;
        }
        wconv_body(W, wl + (size_t)layer * LAYER_W_ELEMS, rem & 7, rem >> 3, 16);
    }
}

// ---------------- HMMA bf16x3 GEMM (R8 schedule) ----------------
// CTA 128(M) x 64(N); grid (16 nb-half, 8 mb, nz). Stage = {Ah,Al,Wh,Wl} = 48KB, NSTAGE=2.
// Warp tile 32(M) x 32(N), 4m x 2n warps, per-i register-pipelined prefetch.
// EPI 0: write fp32 Y. EPI 1: tanh(acc + bias) -> A' paired tiles (TK_out=16).
#define NSTAGE 2
#define STAGE_BYTES 49152
template <int EPI>
__global__ __launch_bounds__(256, 2)
void mma_gemm(const __nv_bfloat16* __restrict__ Ab, size_t az,
              const __nv_bfloat16* __restrict__ Wb, size_t wz,
              float* __restrict__ Yb, size_t yz, int TK,
              const float* __restrict__ bias, __nv_bfloat16* __restrict__ Aout) {
    extern __shared__ char smem[];
    uint32_t base = smem_u32(smem);
    uint32_t tbase = (base + 1023u) & ~1023u;
    uint32_t ctrl = tbase + NSTAGE * STAGE_BYTES;

    int tid = threadIdx.x;
    int wid = tid >> 5, lane = tid & 31;
    int wm = (wid & 3) * 32;     // 4 m-warps
    int wn = (wid >> 2) * 32;    // 2 n-warps
    int z = blockIdx.z;

    if (tid == 0) { mbar_init(ctrl, 1); mbar_init(ctrl + 8, 1); }
    __syncthreads();

    const char* Aptr = (const char*)(Ab + (size_t)z * az) + (size_t)blockIdx.y * TK * 32768;
    const char* Wptr = (const char*)(Wb + (size_t)z * wz) + (size_t)(blockIdx.x >> 1) * TK * 32768;
    uint32_t bhalf = (blockIdx.x & 1) * 8192u;

    if (tid == 0) {
        #pragma unroll
        for (int i = 0; i < NSTAGE; ++i) {
            uint32_t mb = ctrl + i * 8;
            mbar_expect_tx(mb, STAGE_BYTES);
            bulk_g2s(tbase + i * STAGE_BYTES,         Aptr + (size_t)i * 32768, 32768u, mb);
            bulk_g2s(tbase + i * STAGE_BYTES + 32768, Wptr + (size_t)i * 32768 + bhalf, 8192u, mb);
            bulk_g2s(tbase + i * STAGE_BYTES + 40960, Wptr + (size_t)i * 32768 + 16384 + bhalf, 8192u, mb);
        }
    }

    int rA[2], xA[2];
    #pragma unroll
    for (int i = 0; i < 2; ++i) {
        int row = wm + i * 16 + (lane & 15);
        rA[i] = row * 128;
        xA[i] = (row & 7) << 4;
    }
    int hiA = (lane >> 4) << 4;
    int rowB = wn + (lane & 7) + ((lane >> 4) << 3);
    int rB = rowB * 128;                 // group 0; group 1 at +16 rows = +2048B
    int xB = (rowB & 7) << 4;
    int hiB = ((lane >> 3) & 1) << 4;

    float acc[2][4][4];
    #pragma unroll
    for (int i = 0; i < 2; ++i)
        #pragma unroll
        for (int j = 0; j < 4; ++j)
            #pragma unroll
            for (int q = 0; q < 4; ++q) acc[i][j][q] = 0.f;

    for (int kt = 0; kt < TK; ++kt) {
        int s = kt & 1;
        mbar_wait(ctrl + s * 8, (kt >> 1) & 1);
        uint32_t sAh = tbase + s * STAGE_BYTES;
        uint32_t sAl = sAh + 16384u;
        uint32_t sWh = sAh + 32768u;
        uint32_t sWl = sAh + 40960u;

        uint32_t ah[2][4], al[2][4], wh[2][8], wl[2][8];
        // preload kk=0: B both col-groups, A i=0
        {
            uint32_t boff = (uint32_t)hiB ^ (uint32_t)xB;
            ldsm4(wh[0][0], wh[0][1], wh[0][2], wh[0][3], sWh + rB + boff);
            ldsm4(wh[0][4], wh[0][5], wh[0][6], wh[0][7], sWh + rB + 2048 + boff);
            ldsm4(wl[0][0], wl[0][1], wl[0][2], wl[0][3], sWl + rB + boff);
            ldsm4(wl[0][4], wl[0][5], wl[0][6], wl[0][7], sWl + rB + 2048 + boff);
            uint32_t aoff = (uint32_t)hiA ^ (uint32_t)xA[0];
            ldsm4(ah[0][0], ah[0][1], ah[0][2], ah[0][3], sAh + rA[0] + aoff);
            ldsm4(al[0][0], al[0][1], al[0][2], al[0][3], sAl + rA[0] + aoff);
        }
        #pragma unroll
        for (int kk = 0; kk < 4; ++kk) {
            const int bb = kk & 1;
            #pragma unroll
            for (int i = 0; i < 2; ++i) {
                const int ab = (kk * 2 + i) & 1;
                if (i == 0) {
                    uint32_t aoff = (uint32_t)((kk << 5) + hiA) ^ (uint32_t)xA[1];
                    ldsm4(ah[ab ^ 1][0], ah[ab ^ 1][1], ah[ab ^ 1][2], ah[ab ^ 1][3], sAh + rA[1] + aoff);
                    ldsm4(al[ab ^ 1][0], al[ab ^ 1][1], al[ab ^ 1][2], al[ab ^ 1][3], sAl + rA[1] + aoff);
                } else if (kk < 3) {
                    uint32_t boff = (uint32_t)(((kk + 1) << 5) + hiB) ^ (uint32_t)xB;
                    ldsm4(wh[bb ^ 1][0], wh[bb ^ 1][1], wh[bb ^ 1][2], wh[bb ^ 1][3], sWh + rB + boff);
                    ldsm4(wh[bb ^ 1][4], wh[bb ^ 1][5], wh[bb ^ 1][6], wh[bb ^ 1][7], sWh + rB + 2048 + boff);
                    ldsm4(wl[bb ^ 1][0], wl[bb ^ 1][1], wl[bb ^ 1][2], wl[bb ^ 1][3], sWl + rB + boff);
                    ldsm4(wl[bb ^ 1][4], wl[bb ^ 1][5], wl[bb ^ 1][6], wl[bb ^ 1][7], sWl + rB + 2048 + boff);
                    uint32_t aoff = (uint32_t)(((kk + 1) << 5) + hiA) ^ (uint32_t)xA[0];
                    ldsm4(ah[ab ^ 1][0], ah[ab ^ 1][1], ah[ab ^ 1][2], ah[ab ^ 1][3], sAh + rA[0] + aoff);
                    ldsm4(al[ab ^ 1][0], al[ab ^ 1][1], al[ab ^ 1][2], al[ab ^ 1][3], sAl + rA[0] + aoff);
                }
                mma16816(acc[i][0], ah[ab], wh[bb][0], wh[bb][1]);
                mma16816(acc[i][1], ah[ab], wh[bb][2], wh[bb][3]);
                mma16816(acc[i][2], ah[ab], wh[bb][4], wh[bb][5]);
                mma16816(acc[i][3], ah[ab], wh[bb][6], wh[bb][7]);
                mma16816(acc[i][0], ah[ab], wl[bb][0], wl[bb][1]);
                mma16816(acc[i][1], ah[ab], wl[bb][2], wl[bb][3]);
                mma16816(acc[i][2], ah[ab], wl[bb][4], wl[bb][5]);
                mma16816(acc[i][3], ah[ab], wl[bb][6], wl[bb][7]);
                mma16816(acc[i][0], al[ab], wh[bb][0], wh[bb][1]);
                mma16816(acc[i][1], al[ab], wh[bb][2], wh[bb][3]);
                mma16816(acc[i][2], al[ab], wh[bb][4], wh[bb][5]);
                mma16816(acc[i][3], al[ab], wh[bb][6], wh[bb][7]);
            }
        }
        __syncthreads();
        if (tid == 0 && kt + NSTAGE < TK) {
            int nk = kt + NSTAGE;
            uint32_t mb = ctrl + s * 8;
            mbar_expect_tx(mb, STAGE_BYTES);
            bulk_g2s(sAh,          Aptr + (size_t)nk * 32768, 32768u, mb);
            bulk_g2s(sAh + 32768u, Wptr + (size_t)nk * 32768 + bhalf, 8192u, mb);
            bulk_g2s(sAh + 40960u, Wptr + (size_t)nk * 32768 + 16384 + bhalf, 8192u, mb);
        }
    }

    int trow0 = wm + (lane >> 2);
    if (EPI == 0) {
        float* Y = Yb + (size_t)z * yz;
        int r0 = blockIdx.y * 128 + trow0;
        #pragma unroll
        for (int i = 0; i < 2; ++i) {
            #pragma unroll
            for (int j = 0; j < 4; ++j) {
                int row = r0 + i * 16;
                int col = blockIdx.x * 64 + wn + j * 8 + ((lane & 3) << 1);
                *(float2*)&Y[(size_t)row * 1024 + col]       = make_float2(acc[i][j][0], acc[i][j][1]);
                *(float2*)&Y[(size_t)(row + 8) * 1024 + col] = make_float2(acc[i][j][2], acc[i][j][3]);
            }
        }
    } else {
        #pragma unroll
        for (int i = 0; i < 2; ++i) {
            #pragma unroll
            for (int j = 0; j < 4; ++j) {
                int col = blockIdx.x * 64 + wn + j * 8 + ((lane & 3) << 1);
                float b0 = bias[col], b1 = bias[col + 1];
                float v00 = tanhf(acc[i][j][0] + b0);
                float v01 = tanhf(acc[i][j][1] + b1);
                float v10 = tanhf(acc[i][j][2] + b0);
                float v11 = tanhf(acc[i][j][3] + b1);
                store_pair2(Aout, blockIdx.y, 16, trow0 + i * 16,     col, v00, v01);
                store_pair2(Aout, blockIdx.y, 16, trow0 + i * 16 + 8, col, v10, v11);
            }
        }
    }
    __syncthreads();
    if (tid == 0) { mbar_inval(ctrl); mbar_inval(ctrl + 8); }
}

// ---------------- BatchNorm(+tanh), batched over z ----------------
template <bool TILES, bool FP32>
__global__ __launch_bounds__(256)
void bn_kernel(const float* __restrict__ Yb, size_t yz,
               const float* __restrict__ g0, const float* __restrict__ g1, const float* __restrict__ g2,
               const float* __restrict__ be0, const float* __restrict__ be1, const float* __restrict__ be2,
               float* __restrict__ afpB, size_t afz,
               __nv_bfloat16* __restrict__ AtB, size_t atz) {
    __shared__ float ss[32][8], sq[32][8];
    __shared__ float sscale[8], sshift[8];
    int z = blockIdx.y;
    const float* Y   = Yb + (size_t)z * yz;
    const float* g    = (z == 0) ? g0 : (z == 1) ? g1 : g2;
    const float* beta = (z == 0) ? be0 : (z == 1) ? be1 : be2;
    int tid = threadIdx.x;
    int c0 = blockIdx.x * 8;
    int c = tid & 7, rg = tid >> 3;
    float s = 0.f, q = 0.f;
    for (int r = rg; r < 1024; r += 32) {
        float v = Y[(size_t)r * 1024 + c0 + c];
        s += v; q += v * v;
    }
    ss[rg][c] = s; sq[rg][c] = q;
    __syncthreads();
    if (tid < 8) {
        float ts = 0.f, tq = 0.f;
        #pragma unroll
        for (int i = 0; i < 32; ++i) { ts += ss[i][tid]; tq += sq[i][tid]; }
        float mean = ts * (1.f / 1024.f);
        float var  = fmaxf(tq * (1.f / 1024.f) - mean * mean, 0.f);
        float rs   = rsqrtf(var + 1e-5f);
        float sc   = g[c0 + tid] * rs;
        sscale[tid] = sc;
        sshift[tid] = beta[c0 + tid] - mean * sc;
    }
    __syncthreads();
    float sc[8], sh[8];
    #pragma unroll
    for (int i = 0; i < 8; ++i) { sc[i] = sscale[i]; sh[i] = sshift[i]; }
    float* afp = FP32 ? (afpB + (size_t)z * afz) : nullptr;
    __nv_bfloat16* At = TILES ? (AtB + (size_t)z * atz) : nullptr;
    for (int r = tid; r < 1024; r += 256) {
        float4 v0 = *(const float4*)&Y[(size_t)r * 1024 + c0];
        float4 v1 = *(const float4*)&Y[(size_t)r * 1024 + c0 + 4];
        float v[8] = {v0.x, v0.y, v0.z, v0.w, v1.x, v1.y, v1.z, v1.w};
        #pragma unroll
        for (int i = 0; i < 8; ++i) v[i] = tanhf(v[i] * sc[i] + sh[i]);
        if (FP32) {
            *(float4*)&afp[(size_t)r * 1024 + c0]     = make_float4(v[0], v[1], v[2], v[3]);
            *(float4*)&afp[(size_t)r * 1024 + c0 + 4] = make_float4(v[4], v[5], v[6], v[7]);
        }
        if (TILES) {
            uint4 hi, lo;
            split8(v, hi, lo);
            store_pair(At, r >> 7, 16, r & 127, c0, hi, lo);
        }
    }
}

// ---------------- batched head GEMMs: grid (128, 3) ----------------
__global__ __launch_bounds__(128)
void final_kernel(const float* __restrict__ Xb, size_t xz,
                  const float* __restrict__ wf0, const float* __restrict__ wf1, const float* __restrict__ wf2,
                  const float* __restrict__ bf0, const float* __restrict__ bf1, const float* __restrict__ bf2,
                  float* __restrict__ outb) {
    __shared__ float sh[8][1024];
    int t = blockIdx.y;
    const int nout = (t == 0) ? 7 : (t == 1) ? 5 : 102;
    const int off  = (t == 0) ? 0 : (t == 1) ? 7 * NSEG : 12 * NSEG;
    const float* X  = Xb + (size_t)t * xz;
    const float* Wf = (t == 0) ? wf0 : (t == 1) ? wf1 : wf2;
    const float* bf = (t == 0) ? bf0 : (t == 1) ? bf1 : bf2;
    float* out = outb + off;

    int r0 = blockIdx.x * 8;
    const float4* Xs = (const float4*)(X + (size_t)r0 * 1024);
    #pragma unroll
    for (int q = 0; q < 16; ++q) {
        int i = threadIdx.x + q * 128;
        int row = i >> 8, col4 = (i & 255);
        *(float4*)&sh[row][col4 * 4] = Xs[(size_t)row * 256 + col4];
    }
    __syncthreads();
    for (int n = threadIdx.x; n < nout; n += 128) {
        float acc[8];
        float bv = bf[n];
        #pragma unroll
        for (int r = 0; r < 8; ++r) acc[r] = bv;
        #pragma unroll 8
        for (int k = 0; k < 1024; ++k) {
            float w = Wf[(size_t)k * nout + n];
            #pragma unroll
            for (int r = 0; r < 8; ++r) acc[r] += sh[r][k] * w;
        }
        #pragma unroll
        for (int r = 0; r < 8; ++r)
            out[(size_t)(r0 + r) * nout + n] = acc[r];
    }
}

// ---------------- launch ----------------
#define GEMM_SMEM (NSTAGE * STAGE_BYTES + 1024 + 64)

extern "C" void kernel_launch(void* const* d_in, const int* in_sizes, int n_in,
                              void* d_out, int out_size) {
    const float* h        = (const float*)d_in[0];
    const int*   turns    = (const int*)  d_in[1];
    const int*   parts    = (const int*)  d_in[2];
    const float* pooler_W = (const float*)d_in[3];
    const float* pooler_b = (const float*)d_in[4];
    const float* pool_W   = (const float*)d_in[5];
    // d_in[6] pool_b: cancelled by BN mean subtraction
    const float* pool_g   = (const float*)d_in[7];
    const float* pool_be  = (const float*)d_in[8];
    const float* emo_Ws   = (const float*)d_in[9];
    const float* emo_gs   = (const float*)d_in[11];
    const float* emo_be   = (const float*)d_in[12];
    const float* emo_Wf   = (const float*)d_in[13];
    const float* emo_bf   = (const float*)d_in[14];
    const float* act_Ws   = (const float*)d_in[15];
    const float* act_gs   = (const float*)d_in[17];
    const float* act_be   = (const float*)d_in[18];
    const float* act_Wf   = (const float*)d_in[19];
    const float* act_bf   = (const float*)d_in[20];
    const float* int_Ws   = (const float*)d_in[21];
    const float* int_gs   = (const float*)d_in[23];
    const float* int_be   = (const float*)d_in[24];
    const float* int_Wf   = (const float*)d_in[25];
    const float* int_bf   = (const float*)d_in[26];
    float* out = (float*)d_out;

    __nv_bfloat16 *Wbf, *Abf, *Ax, *Ap;
    float *y, *a;
    cudaGetSymbolAddress((void**)&Wbf, g_Wbf);
    cudaGetSymbolAddress((void**)&Abf, g_Abf);
    cudaGetSymbolAddress((void**)&Ax,  g_Ax);
    cudaGetSymbolAddress((void**)&Ap,  g_Ap);
    cudaGetSymbolAddress((void**)&y,   g_y);
    cudaGetSymbolAddress((void**)&a,   g_a);
    __nv_bfloat16* wl = Wbf + POOLER_W_ELEMS;

    cudaFuncSetAttribute(mma_gemm<0>, cudaFuncAttributeMaxDynamicSharedMemorySize, GEMM_SMEM);
    cudaFuncSetAttribute(mma_gemm<1>, cudaFuncAttributeMaxDynamicSharedMemorySize, GEMM_SMEM);

    // merged prep: pooling + all weight conversions in ONE launch (independent work overlaps)
    prep_kernel<<<2944, 256>>>(h, turns, parts, Abf, pooler_W, Wbf,
                               pool_W, emo_Ws, act_Ws, int_Ws, wl);

    // pooler GEMM + fused tanh(+bias) epilogue -> A'(x0) in Ax[0]
    mma_gemm<1><<<dim3(16, 8, 1), 256, GEMM_SMEM>>>(Abf, 0, Wbf, 0, nullptr, 0, 32, pooler_b, Ax);

    // pool Linear_Block -> Ap (shared input of all 3 towers)
    mma_gemm<0><<<dim3(16, 8, 1), 256, GEMM_SMEM>>>(Ax, 0, wl, 0, y, 0, 16, nullptr, nullptr);
    bn_kernel<true, false><<<dim3(128, 1), 256>>>(y, 0, pool_g, pool_g, pool_g,
                                                  pool_be, pool_be, pool_be,
                                                  nullptr, 0, Ap, 0);

    // tower depths, batched over the 3 towers
    for (int k = 0; k < 4; ++k) {
        const __nv_bfloat16* Ain = (k == 0) ? Ap : Ax;
        size_t az = (k == 0) ? 0 : (size_t)AX_STRIDE;
        mma_gemm<0><<<dim3(16, 8, 3), 256, GEMM_SMEM>>>(Ain, az,
                                                        wl + (size_t)(1 + k) * LAYER_W_ELEMS,
                                                        (size_t)4 * LAYER_W_ELEMS,
                                                        y, Y_STRIDE, 16, nullptr, nullptr);
        if (k < 3)
            bn_kernel<true, false><<<dim3(128, 3), 256>>>(y, Y_STRIDE,
                emo_gs + k * DIM, act_gs + k * DIM, int_gs + k * DIM,
                emo_be + k * DIM, act_be + k * DIM, int_be + k * DIM,
                nullptr, 0, Ax, AX_STRIDE);
        else
            bn_kernel<false, true><<<dim3(128, 3), 256>>>(y, Y_STRIDE,
                emo_gs + k * DIM, act_gs + k * DIM, int_gs + k * DIM,
                emo_be + k * DIM, act_be + k * DIM, int_be + k * DIM,
                a, Y_STRIDE, nullptr, 0);
    }

    // batched heads
    final_kernel<<<dim3(128, 3), 128>>>(a, Y_STRIDE, emo_Wf, act_Wf, int_Wf,
                                        emo_bf, act_bf, int_bf, out);
}